// round 13
// baseline (speedup 1.0000x reference)
#include <cuda_runtime.h>
#include <math.h>

#define V 50257
#define H 1024
#define S 2048
#define NATTN 128               // attention blocks (wave-1 resident by ID)
#define NBK 6283                // ceil(V/8), 8 rows per logits block
#define GRID_A (NATTN + NBK)

// out layout: [0,V) log_softmax | [V,V+H) context | [V+H,V+3H) hidden | [V+3H,V+3H+S) attn
#define OUT_CTX  (V)
#define OUT_HID  (V + H)
#define OUT_ATTN (V + 3*H)

// float4-accessed globals MUST be 16B aligned (round-4 trap)
__device__ __align__(16) float g_h0[H];
__device__ __align__(16) float g_h1[H];
__device__ __align__(16) float g_v[H];
__device__ __align__(16) float g_context[H];
__device__ __align__(16) float g_logits[V];
__device__ __align__(16) float g_part[NBK * 8];   // h1-half partial per row
__device__ __align__(16) float g_gh1[3 * H];      // GRU1 hidden-gate partials
__device__ float g_apm[NATTN];
__device__ float g_aps[NATTN];
__device__ float g_sumexpv;        // global sum of exp(logit), shift 0 (logits are O(1))
__device__ unsigned g_barrier;     // attention-internal barrier

__device__ __forceinline__ float warp_sum(float v) {
    #pragma unroll
    for (int o = 16; o; o >>= 1) v += __shfl_down_sync(0xffffffffu, v, o);
    return v;
}
__device__ __forceinline__ float warp_max(float v) {
    #pragma unroll
    for (int o = 16; o; o >>= 1) v = fmaxf(v, __shfl_down_sync(0xffffffffu, v, o));
    return v;
}
__device__ __forceinline__ float dot4(float4 a, float4 b) {
    return a.x*b.x + a.y*b.y + a.z*b.z + a.w*b.w;
}
// barrier among the NATTN attention blocks only (IDs 0..127 -> wave-1 resident)
__device__ __forceinline__ void attn_barrier(unsigned target) {
    __syncthreads();
    if (threadIdx.x == 0) {
        __threadfence();
        atomicAdd(&g_barrier, 1u);
        volatile unsigned* p = &g_barrier;
        while (*p < target) __nanosleep(32);
        __threadfence();
    }
    __syncthreads();
}

// ---------------- G1: blocks [0,H): GRU0 row k (x = [emb[word], last_ctx]).
// blocks [H,2H): GRU1 hidden-gate partials gh1 = W_hh1 · last_hid1 (indep of h0).
__global__ void __launch_bounds__(256) kG1(const int* __restrict__ word,
                                           const float* __restrict__ emb,
                                           const float* __restrict__ last_ctx,
                                           const float* __restrict__ last_hid,
                                           const float* __restrict__ W_ih0,
                                           const float* __restrict__ W_hh0,
                                           const float* __restrict__ b_ih0,
                                           const float* __restrict__ b_hh0,
                                           const float* __restrict__ W_hh1,
                                           float* __restrict__ out_hidden0) {
    const int t = threadIdx.x;                 // 256
    const int w = t >> 5, lane = t & 31;
    __shared__ float red[6][8];

    if (blockIdx.x < H) {
        // ===== GRU0 row k =====
        const int k = blockIdx.x;
        if (t == 0) {
            g_v[k] = 0.f;
            g_context[k] = 0.f;
            if (k == 0) { g_barrier = 0u; g_sumexpv = 0.f; }
        }
        int wi = word[0];
        const float4* xa4 = (const float4*)(emb + (size_t)wi * H);
        const float4* xb4 = (const float4*)last_ctx;
        const float4* h4  = (const float4*)last_hid;      // hidden layer 0
        float acc[6];
        #pragma unroll
        for (int g = 0; g < 3; g++) {
            const float* wrow = W_ih0 + (size_t)(g * H + k) * (2*H);
            float a  = dot4(((const float4*)wrow)[t],       xa4[t]);
            a       += dot4(((const float4*)(wrow + H))[t], xb4[t]);
            acc[g] = a;
        }
        #pragma unroll
        for (int g = 0; g < 3; g++) {
            const float* wrow = W_hh0 + (size_t)(g * H + k) * H;
            acc[3 + g] = dot4(((const float4*)wrow)[t], h4[t]);
        }
        #pragma unroll
        for (int g = 0; g < 6; g++) {
            float s = warp_sum(acc[g]);
            if (lane == 0) red[g][w] = s;
        }
        __syncthreads();
        if (t == 0) {
            float s[6];
            #pragma unroll
            for (int g = 0; g < 6; g++) {
                float a = 0.f;
                #pragma unroll
                for (int j = 0; j < 8; j++) a += red[g][j];
                s[g] = a;
            }
            float ir = s[0] + b_ih0[k],       hr = s[3] + b_hh0[k];
            float iz = s[1] + b_ih0[H + k],   hz = s[4] + b_hh0[H + k];
            float in_= s[2] + b_ih0[2*H + k], hn = s[5] + b_hh0[2*H + k];
            float r = 1.f / (1.f + expf(-(ir + hr)));
            float z = 1.f / (1.f + expf(-(iz + hz)));
            float n = tanhf(in_ + r * hn);
            float hv = (1.f - z) * n + z * last_hid[k];
            g_h0[k] = hv;
            out_hidden0[k] = hv;
        }
    } else {
        // ===== GRU1 gh partials for row k =====
        const int k = blockIdx.x - H;
        const float4* h4 = (const float4*)(last_hid + H); // hidden layer 1
        float acc[3];
        #pragma unroll
        for (int g = 0; g < 3; g++) {
            const float* wrow = W_hh1 + (size_t)(g * H + k) * H;
            acc[g] = dot4(((const float4*)wrow)[t], h4[t]);
        }
        #pragma unroll
        for (int g = 0; g < 3; g++) {
            float s = warp_sum(acc[g]);
            if (lane == 0) red[g][w] = s;
        }
        __syncthreads();
        if (t == 0) {
            #pragma unroll
            for (int g = 0; g < 3; g++) {
                float a = 0.f;
                #pragma unroll
                for (int j = 0; j < 8; j++) a += red[g][j];
                g_gh1[g * H + k] = a;
            }
        }
    }
}

// ---------------- G2: GRU1 input gates gi = W_ih1 · h0; combine with g_gh1.
__global__ void __launch_bounds__(256) kG2(const float* __restrict__ W_ih1,
                                           const float* __restrict__ b_ih1,
                                           const float* __restrict__ b_hh1,
                                           const float* __restrict__ last_hid,
                                           float* __restrict__ out_hidden1) {
    const int k = blockIdx.x;
    const int t = threadIdx.x;
    const int w = t >> 5, lane = t & 31;
    __shared__ float red[3][8];
    const float4* x4 = (const float4*)g_h0;
    float acc[3];
    #pragma unroll
    for (int g = 0; g < 3; g++) {
        const float* wrow = W_ih1 + (size_t)(g * H + k) * H;
        acc[g] = dot4(((const float4*)wrow)[t], x4[t]);
    }
    #pragma unroll
    for (int g = 0; g < 3; g++) {
        float s = warp_sum(acc[g]);
        if (lane == 0) red[g][w] = s;
    }
    __syncthreads();
    if (t == 0) {
        float s[3];
        #pragma unroll
        for (int g = 0; g < 3; g++) {
            float a = 0.f;
            #pragma unroll
            for (int j = 0; j < 8; j++) a += red[g][j];
            s[g] = a;
        }
        float hprev = last_hid[H + k];
        float ir = s[0] + b_ih1[k],       hr = g_gh1[k]       + b_hh1[k];
        float iz = s[1] + b_ih1[H + k],   hz = g_gh1[H + k]   + b_hh1[H + k];
        float in_= s[2] + b_ih1[2*H + k], hn = g_gh1[2*H + k] + b_hh1[2*H + k];
        float r = 1.f / (1.f + expf(-(ir + hr)));
        float z = 1.f / (1.f + expf(-(iz + hz)));
        float n = tanhf(in_ + r * hn);
        float hv = (1.f - z) * n + z * hprev;
        g_h1[k] = hv;
        out_hidden1[k] = hv;
    }
}

// ---------------- Kernel A: blocks [0,NATTN) fused attention (independent);
// blocks [NATTN,GRID_A): h1-half of W_out rows (1 row/warp, __ldcs) -> g_part.
// lb(256,8): push to 8 blocks/SM (64 warps) for deeper latency hiding.
__global__ void __launch_bounds__(256, 8) kA(const float* __restrict__ Wa,
                                             const float* __restrict__ enc,
                                             const float* __restrict__ Wout,
                                             float* __restrict__ out_attn) {
    const int t = threadIdx.x;
    const int w = t >> 5, lane = t & 31;

    if (blockIdx.x < NATTN) {
        // ===== attention =====
        const int b = blockIdx.x;
        __shared__ float h1s[8];
        __shared__ float sc[16];
        __shared__ float attnw[16];
        __shared__ float red[8];
        __shared__ float sM, sInvS;

        if (t < 8) h1s[t] = g_h1[b * 8 + t];
        __syncthreads();
        {
            const float4* Wa4 = (const float4*)(Wa + (size_t)(b * 8) * H);
            float4 a = make_float4(0.f, 0.f, 0.f, 0.f);
            #pragma unroll
            for (int j = 0; j < 8; j++) {
                float4 wv = Wa4[j * 256 + t];
                float hv = h1s[j];
                a.x += wv.x * hv; a.y += wv.y * hv; a.z += wv.z * hv; a.w += wv.w * hv;
            }
            atomicAdd(&g_v[4*t + 0], a.x);
            atomicAdd(&g_v[4*t + 1], a.y);
            atomicAdd(&g_v[4*t + 2], a.z);
            atomicAdd(&g_v[4*t + 3], a.w);
        }
        attn_barrier(NATTN);

        const int s0 = b * 16;
        {
            const float4* v4 = (const float4*)g_v;
            const float4* e4a = (const float4*)(enc + (size_t)(s0 + 2*w)     * H);
            const float4* e4b = (const float4*)(enc + (size_t)(s0 + 2*w + 1) * H);
            float acc0 = 0.f, acc1 = 0.f;
            #pragma unroll
            for (int i = 0; i < 8; i++) {
                float4 vv = v4[lane + 32*i];
                acc0 += dot4(e4a[lane + 32*i], vv);
                acc1 += dot4(e4b[lane + 32*i], vv);
            }
            acc0 = warp_sum(acc0);
            acc1 = warp_sum(acc1);
            if (lane == 0) { sc[2*w] = acc0; sc[2*w + 1] = acc1; }
        }
        __syncthreads();
        if (t == 0) {
            float m = -INFINITY;
            #pragma unroll
            for (int j = 0; j < 16; j++) m = fmaxf(m, sc[j]);
            float s = 0.f;
            #pragma unroll
            for (int j = 0; j < 16; j++) s += expf(sc[j] - m);
            g_apm[b] = m;
            g_aps[b] = s;
        }
        attn_barrier(2 * NATTN);

        {
            float m = (t < NATTN) ? g_apm[t] : -INFINITY;
            m = warp_max(m);
            if (lane == 0) red[w] = m;
            __syncthreads();
            if (t == 0) {
                float M = -INFINITY;
                #pragma unroll
                for (int j = 0; j < 8; j++) M = fmaxf(M, red[j]);
                sM = M;
            }
            __syncthreads();
            float e = (t < NATTN) ? g_aps[t] * expf(g_apm[t] - sM) : 0.f;
            e = warp_sum(e);
            if (lane == 0) red[w] = e;
            __syncthreads();
            if (t == 0) {
                float Ssum = 0.f;
                #pragma unroll
                for (int j = 0; j < 8; j++) Ssum += red[j];
                sInvS = 1.f / Ssum;
            }
            __syncthreads();
            if (t < 16) {
                float a = expf(sc[t] - sM) * sInvS;
                attnw[t] = a;
                out_attn[s0 + t] = a;
            }
            __syncthreads();
        }
        {
            const float4* e4 = (const float4*)(enc + (size_t)s0 * H);
            float4 c = make_float4(0.f, 0.f, 0.f, 0.f);
            #pragma unroll
            for (int r = 0; r < 16; r++) {
                float av = attnw[r];
                float4 e = e4[r * 256 + t];
                c.x += av * e.x; c.y += av * e.y; c.z += av * e.z; c.w += av * e.w;
            }
            atomicAdd(&g_context[4*t + 0], c.x);
            atomicAdd(&g_context[4*t + 1], c.y);
            atomicAdd(&g_context[4*t + 2], c.z);
            atomicAdd(&g_context[4*t + 3], c.w);
        }
    } else {
        // ===== h1-half logits partial (cols [0,H)), 1 row/warp, streaming =====
        const int bb = blockIdx.x - NATTN;
        __shared__ __align__(16) float qs[H];
        for (int i = t; i < H; i += 256) qs[i] = g_h1[i];
        __syncthreads();
        const int r = bb * 8 + w;
        if (r < V) {
            const float4* wr = (const float4*)(Wout + (size_t)r * (2*H));
            const float4* q4 = (const float4*)qs;
            float acc0 = 0.f, acc1 = 0.f;
            #pragma unroll
            for (int i = 0; i < 8; i += 2) {
                acc0 += dot4(__ldcs(&wr[lane + i*32]),     q4[lane + i*32]);
                acc1 += dot4(__ldcs(&wr[lane + (i+1)*32]), q4[lane + (i+1)*32]);
            }
            float acc = warp_sum(acc0 + acc1);
            if (lane == 0) g_part[r] = acc;
        }
    }
}

// ---------------- Kernel B: ctx-half (cols [H,2H)), 1 row/warp, __ldcs; combine
// -> logits; block sum-exp (shift 0 — logits are O(1)). lb(256,8).
__global__ void __launch_bounds__(256, 8) kB(const float* __restrict__ Wout,
                                             const float* __restrict__ bout) {
    const int t = threadIdx.x;
    const int w = t >> 5, lane = t & 31;
    __shared__ __align__(16) float qs[H];
    __shared__ float bexp[8];
    for (int i = t; i < H; i += 256) qs[i] = g_context[i];
    __syncthreads();

    const int r = blockIdx.x * 8 + w;
    float e = 0.f;
    if (r < V) {
        const float4* wr = (const float4*)(Wout + (size_t)r * (2*H) + H);
        const float4* q4 = (const float4*)qs;
        float acc0 = 0.f, acc1 = 0.f;
        #pragma unroll
        for (int i = 0; i < 8; i += 2) {
            acc0 += dot4(__ldcs(&wr[lane + i*32]),     q4[lane + i*32]);
            acc1 += dot4(__ldcs(&wr[lane + (i+1)*32]), q4[lane + (i+1)*32]);
        }
        float acc = warp_sum(acc0 + acc1);
        if (lane == 0) {
            float logit = acc + g_part[r] + bout[r];
            g_logits[r] = logit;
            e = expf(logit);
        }
    }
    if (lane == 0) bexp[w] = e;
    __syncthreads();
    if (t == 0) {
        float s = 0.f;
        #pragma unroll
        for (int j = 0; j < 8; j++) s += bexp[j];
        atomicAdd(&g_sumexpv, s);
    }
}

// ---------------- K9: elementwise normalize; block 0 emits context.
__global__ void __launch_bounds__(256) k9_final(float* __restrict__ out,
                                                float* __restrict__ out_ctx) {
    const int t = threadIdx.x;
    if (blockIdx.x == 0) {
        for (int i = t; i < H; i += 256) out_ctx[i] = g_context[i];
    }
    float shift = logf(g_sumexpv);
    int v = blockIdx.x * 256 + t;
    if (v < V) out[v] = g_logits[v] - shift;
}

extern "C" void kernel_launch(void* const* d_in, const int* in_sizes, int n_in,
                              void* d_out, int out_size) {
    const int*   word     = (const int*)  d_in[0];
    const float* last_ctx = (const float*)d_in[1];
    const float* last_hid = (const float*)d_in[2];
    const float* enc      = (const float*)d_in[3];
    const float* emb      = (const float*)d_in[4];
    const float* W_ih0    = (const float*)d_in[5];
    const float* W_hh0    = (const float*)d_in[6];
    const float* b_ih0    = (const float*)d_in[7];
    const float* b_hh0    = (const float*)d_in[8];
    const float* W_ih1    = (const float*)d_in[9];
    const float* W_hh1    = (const float*)d_in[10];
    const float* b_ih1    = (const float*)d_in[11];
    const float* b_hh1    = (const float*)d_in[12];
    const float* Wa       = (const float*)d_in[13];
    // d_in[14] = ba (cancels under softmax shift-invariance)
    const float* W_out    = (const float*)d_in[15];
    const float* b_out    = (const float*)d_in[16];
    float* out = (float*)d_out;

    kG1<<<2*H, 256>>>(word, emb, last_ctx, last_hid,
                      W_ih0, W_hh0, b_ih0, b_hh0, W_hh1,
                      out + OUT_HID);
    kG2<<<H, 256>>>(W_ih1, b_ih1, b_hh1, last_hid, out + OUT_HID + H);
    kA<<<GRID_A, 256>>>(Wa, enc, W_out, out + OUT_ATTN);
    kB<<<NBK, 256>>>(W_out, b_out);
    k9_final<<<(V + 255) / 256, 256>>>(out, out + OUT_CTX);
}

// round 14
// speedup vs baseline: 1.0925x; 1.0925x over previous
#include <cuda_runtime.h>
#include <math.h>

#define V 50257
#define H 1024
#define S 2048
#define NATTN 128               // attention blocks (wave-1 resident by ID)
#define NBK 6283                // ceil(V/8), 8 rows per logits block
#define GRID_A (NATTN + NBK)

// out layout: [0,V) log_softmax | [V,V+H) context | [V+H,V+3H) hidden | [V+3H,V+3H+S) attn
#define OUT_CTX  (V)
#define OUT_HID  (V + H)
#define OUT_ATTN (V + 3*H)

// float4-accessed globals MUST be 16B aligned (round-4 trap)
__device__ __align__(16) float g_h0[H];
__device__ __align__(16) float g_h1[H];
__device__ __align__(16) float g_v[H];
__device__ __align__(16) float g_context[H];
__device__ __align__(16) float g_logits[V];
__device__ __align__(16) float g_part[NBK * 8];   // h1-half partial per row
__device__ __align__(16) float g_gh1[3 * H];      // GRU1 hidden-gate partials
__device__ float g_apm[NATTN];
__device__ float g_aps[NATTN];
__device__ float g_sumexpv;        // global sum of exp(logit), shift 0 (logits are O(1))
__device__ unsigned g_barrier;     // attention-internal barrier

__device__ __forceinline__ float warp_sum(float v) {
    #pragma unroll
    for (int o = 16; o; o >>= 1) v += __shfl_down_sync(0xffffffffu, v, o);
    return v;
}
__device__ __forceinline__ float warp_max(float v) {
    #pragma unroll
    for (int o = 16; o; o >>= 1) v = fmaxf(v, __shfl_down_sync(0xffffffffu, v, o));
    return v;
}
__device__ __forceinline__ float dot4(float4 a, float4 b) {
    return a.x*b.x + a.y*b.y + a.z*b.z + a.w*b.w;
}
// barrier among the NATTN attention blocks only (IDs 0..127 -> wave-1 resident)
__device__ __forceinline__ void attn_barrier(unsigned target) {
    __syncthreads();
    if (threadIdx.x == 0) {
        __threadfence();
        atomicAdd(&g_barrier, 1u);
        volatile unsigned* p = &g_barrier;
        while (*p < target) __nanosleep(32);
        __threadfence();
    }
    __syncthreads();
}

// ---------------- G1: blocks [0,H): GRU0 row k (x = [emb[word], last_ctx]).
// blocks [H,2H): GRU1 hidden-gate partials gh1 = W_hh1 · last_hid1 (indep of h0).
__global__ void __launch_bounds__(256) kG1(const int* __restrict__ word,
                                           const float* __restrict__ emb,
                                           const float* __restrict__ last_ctx,
                                           const float* __restrict__ last_hid,
                                           const float* __restrict__ W_ih0,
                                           const float* __restrict__ W_hh0,
                                           const float* __restrict__ b_ih0,
                                           const float* __restrict__ b_hh0,
                                           const float* __restrict__ W_hh1,
                                           float* __restrict__ out_hidden0) {
    const int t = threadIdx.x;                 // 256
    const int w = t >> 5, lane = t & 31;
    __shared__ float red[6][8];

    if (blockIdx.x < H) {
        // ===== GRU0 row k =====
        const int k = blockIdx.x;
        if (t == 0) {
            g_v[k] = 0.f;
            g_context[k] = 0.f;
            if (k == 0) { g_barrier = 0u; g_sumexpv = 0.f; }
        }
        int wi = word[0];
        const float4* xa4 = (const float4*)(emb + (size_t)wi * H);
        const float4* xb4 = (const float4*)last_ctx;
        const float4* h4  = (const float4*)last_hid;      // hidden layer 0
        float acc[6];
        #pragma unroll
        for (int g = 0; g < 3; g++) {
            const float* wrow = W_ih0 + (size_t)(g * H + k) * (2*H);
            float a  = dot4(((const float4*)wrow)[t],       xa4[t]);
            a       += dot4(((const float4*)(wrow + H))[t], xb4[t]);
            acc[g] = a;
        }
        #pragma unroll
        for (int g = 0; g < 3; g++) {
            const float* wrow = W_hh0 + (size_t)(g * H + k) * H;
            acc[3 + g] = dot4(((const float4*)wrow)[t], h4[t]);
        }
        #pragma unroll
        for (int g = 0; g < 6; g++) {
            float s = warp_sum(acc[g]);
            if (lane == 0) red[g][w] = s;
        }
        __syncthreads();
        if (t == 0) {
            float s[6];
            #pragma unroll
            for (int g = 0; g < 6; g++) {
                float a = 0.f;
                #pragma unroll
                for (int j = 0; j < 8; j++) a += red[g][j];
                s[g] = a;
            }
            float ir = s[0] + b_ih0[k],       hr = s[3] + b_hh0[k];
            float iz = s[1] + b_ih0[H + k],   hz = s[4] + b_hh0[H + k];
            float in_= s[2] + b_ih0[2*H + k], hn = s[5] + b_hh0[2*H + k];
            float r = 1.f / (1.f + expf(-(ir + hr)));
            float z = 1.f / (1.f + expf(-(iz + hz)));
            float n = tanhf(in_ + r * hn);
            float hv = (1.f - z) * n + z * last_hid[k];
            g_h0[k] = hv;
            out_hidden0[k] = hv;
        }
    } else {
        // ===== GRU1 gh partials for row k =====
        const int k = blockIdx.x - H;
        const float4* h4 = (const float4*)(last_hid + H); // hidden layer 1
        float acc[3];
        #pragma unroll
        for (int g = 0; g < 3; g++) {
            const float* wrow = W_hh1 + (size_t)(g * H + k) * H;
            acc[g] = dot4(((const float4*)wrow)[t], h4[t]);
        }
        #pragma unroll
        for (int g = 0; g < 3; g++) {
            float s = warp_sum(acc[g]);
            if (lane == 0) red[g][w] = s;
        }
        __syncthreads();
        if (t == 0) {
            #pragma unroll
            for (int g = 0; g < 3; g++) {
                float a = 0.f;
                #pragma unroll
                for (int j = 0; j < 8; j++) a += red[g][j];
                g_gh1[g * H + k] = a;
            }
        }
    }
}

// ---------------- G2: GRU1 input gates gi = W_ih1 · h0; combine with g_gh1.
__global__ void __launch_bounds__(256) kG2(const float* __restrict__ W_ih1,
                                           const float* __restrict__ b_ih1,
                                           const float* __restrict__ b_hh1,
                                           const float* __restrict__ last_hid,
                                           float* __restrict__ out_hidden1) {
    const int k = blockIdx.x;
    const int t = threadIdx.x;
    const int w = t >> 5, lane = t & 31;
    __shared__ float red[3][8];
    const float4* x4 = (const float4*)g_h0;
    float acc[3];
    #pragma unroll
    for (int g = 0; g < 3; g++) {
        const float* wrow = W_ih1 + (size_t)(g * H + k) * H;
        acc[g] = dot4(((const float4*)wrow)[t], x4[t]);
    }
    #pragma unroll
    for (int g = 0; g < 3; g++) {
        float s = warp_sum(acc[g]);
        if (lane == 0) red[g][w] = s;
    }
    __syncthreads();
    if (t == 0) {
        float s[3];
        #pragma unroll
        for (int g = 0; g < 3; g++) {
            float a = 0.f;
            #pragma unroll
            for (int j = 0; j < 8; j++) a += red[g][j];
            s[g] = a;
        }
        float hprev = last_hid[H + k];
        float ir = s[0] + b_ih1[k],       hr = g_gh1[k]       + b_hh1[k];
        float iz = s[1] + b_ih1[H + k],   hz = g_gh1[H + k]   + b_hh1[H + k];
        float in_= s[2] + b_ih1[2*H + k], hn = g_gh1[2*H + k] + b_hh1[2*H + k];
        float r = 1.f / (1.f + expf(-(ir + hr)));
        float z = 1.f / (1.f + expf(-(iz + hz)));
        float n = tanhf(in_ + r * hn);
        float hv = (1.f - z) * n + z * hprev;
        g_h1[k] = hv;
        out_hidden1[k] = hv;
    }
}

// ---------------- Kernel A: blocks [0,NATTN) fused attention (independent);
// blocks [NATTN,GRID_A): h1-half of W_out rows (1 row/warp, __ldcs) -> g_part.
// lb(256,6): measured best (R12). lb(256,8) clamps regs->32, kills per-warp
// MLP, DRAM% drops (R13). Do not change.
__global__ void __launch_bounds__(256, 6) kA(const float* __restrict__ Wa,
                                             const float* __restrict__ enc,
                                             const float* __restrict__ Wout,
                                             float* __restrict__ out_attn) {
    const int t = threadIdx.x;
    const int w = t >> 5, lane = t & 31;

    if (blockIdx.x < NATTN) {
        // ===== attention =====
        const int b = blockIdx.x;
        __shared__ float h1s[8];
        __shared__ float sc[16];
        __shared__ float attnw[16];
        __shared__ float red[8];
        __shared__ float sM, sInvS;

        if (t < 8) h1s[t] = g_h1[b * 8 + t];
        __syncthreads();
        {
            const float4* Wa4 = (const float4*)(Wa + (size_t)(b * 8) * H);
            float4 a = make_float4(0.f, 0.f, 0.f, 0.f);
            #pragma unroll
            for (int j = 0; j < 8; j++) {
                float4 wv = Wa4[j * 256 + t];
                float hv = h1s[j];
                a.x += wv.x * hv; a.y += wv.y * hv; a.z += wv.z * hv; a.w += wv.w * hv;
            }
            atomicAdd(&g_v[4*t + 0], a.x);
            atomicAdd(&g_v[4*t + 1], a.y);
            atomicAdd(&g_v[4*t + 2], a.z);
            atomicAdd(&g_v[4*t + 3], a.w);
        }
        attn_barrier(NATTN);

        const int s0 = b * 16;
        {
            const float4* v4 = (const float4*)g_v;
            float4 vv[8];
            #pragma unroll
            for (int i = 0; i < 8; i++) vv[i] = v4[lane + 32*i];
            const float4* e4a = (const float4*)(enc + (size_t)(s0 + 2*w)     * H);
            const float4* e4b = (const float4*)(enc + (size_t)(s0 + 2*w + 1) * H);
            float acc0 = 0.f, acc1 = 0.f;
            #pragma unroll
            for (int i = 0; i < 8; i++) {
                acc0 += dot4(e4a[lane + 32*i], vv[i]);
                acc1 += dot4(e4b[lane + 32*i], vv[i]);
            }
            acc0 = warp_sum(acc0);
            acc1 = warp_sum(acc1);
            if (lane == 0) { sc[2*w] = acc0; sc[2*w + 1] = acc1; }
        }
        __syncthreads();
        if (t == 0) {
            float m = -INFINITY;
            #pragma unroll
            for (int j = 0; j < 16; j++) m = fmaxf(m, sc[j]);
            float s = 0.f;
            #pragma unroll
            for (int j = 0; j < 16; j++) s += expf(sc[j] - m);
            g_apm[b] = m;
            g_aps[b] = s;
        }
        attn_barrier(2 * NATTN);

        {
            float m = (t < NATTN) ? g_apm[t] : -INFINITY;
            m = warp_max(m);
            if (lane == 0) red[w] = m;
            __syncthreads();
            if (t == 0) {
                float M = -INFINITY;
                #pragma unroll
                for (int j = 0; j < 8; j++) M = fmaxf(M, red[j]);
                sM = M;
            }
            __syncthreads();
            float e = (t < NATTN) ? g_aps[t] * expf(g_apm[t] - sM) : 0.f;
            e = warp_sum(e);
            if (lane == 0) red[w] = e;
            __syncthreads();
            if (t == 0) {
                float Ssum = 0.f;
                #pragma unroll
                for (int j = 0; j < 8; j++) Ssum += red[j];
                sInvS = 1.f / Ssum;
            }
            __syncthreads();
            if (t < 16) {
                float a = expf(sc[t] - sM) * sInvS;
                attnw[t] = a;
                out_attn[s0 + t] = a;
            }
            __syncthreads();
        }
        {
            const float4* e4 = (const float4*)(enc + (size_t)s0 * H);
            float4 c = make_float4(0.f, 0.f, 0.f, 0.f);
            #pragma unroll
            for (int r = 0; r < 16; r++) {
                float av = attnw[r];
                float4 e = e4[r * 256 + t];
                c.x += av * e.x; c.y += av * e.y; c.z += av * e.z; c.w += av * e.w;
            }
            atomicAdd(&g_context[4*t + 0], c.x);
            atomicAdd(&g_context[4*t + 1], c.y);
            atomicAdd(&g_context[4*t + 2], c.z);
            atomicAdd(&g_context[4*t + 3], c.w);
        }
    } else {
        // ===== h1-half logits partial (cols [0,H)), 1 row/warp, streaming =====
        const int bb = blockIdx.x - NATTN;
        __shared__ __align__(16) float qs[H];
        for (int i = t; i < H; i += 256) qs[i] = g_h1[i];
        __syncthreads();
        const int r = bb * 8 + w;
        if (r < V) {
            const float4* wr = (const float4*)(Wout + (size_t)r * (2*H));
            const float4* q4 = (const float4*)qs;
            float acc0 = 0.f, acc1 = 0.f;
            #pragma unroll
            for (int i = 0; i < 8; i += 2) {
                acc0 += dot4(__ldcs(&wr[lane + i*32]),     q4[lane + i*32]);
                acc1 += dot4(__ldcs(&wr[lane + (i+1)*32]), q4[lane + (i+1)*32]);
            }
            float acc = warp_sum(acc0 + acc1);
            if (lane == 0) g_part[r] = acc;
        }
    }
}

// ---------------- Kernel B: ctx-half (cols [H,2H)), 1 row/warp, __ldcs; combine
// -> logits; block sum-exp (shift 0 — logits are O(1)). lb(256,6) measured best.
__global__ void __launch_bounds__(256, 6) kB(const float* __restrict__ Wout,
                                             const float* __restrict__ bout) {
    const int t = threadIdx.x;
    const int w = t >> 5, lane = t & 31;
    __shared__ __align__(16) float qs[H];
    __shared__ float bexp[8];
    for (int i = t; i < H; i += 256) qs[i] = g_context[i];
    __syncthreads();

    const int r = blockIdx.x * 8 + w;
    float e = 0.f;
    if (r < V) {
        const float4* wr = (const float4*)(Wout + (size_t)r * (2*H) + H);
        const float4* q4 = (const float4*)qs;
        float acc0 = 0.f, acc1 = 0.f;
        #pragma unroll
        for (int i = 0; i < 8; i += 2) {
            acc0 += dot4(__ldcs(&wr[lane + i*32]),     q4[lane + i*32]);
            acc1 += dot4(__ldcs(&wr[lane + (i+1)*32]), q4[lane + (i+1)*32]);
        }
        float acc = warp_sum(acc0 + acc1);
        if (lane == 0) {
            float logit = acc + g_part[r] + bout[r];
            g_logits[r] = logit;
            e = expf(logit);
        }
    }
    if (lane == 0) bexp[w] = e;
    __syncthreads();
    if (t == 0) {
        float s = 0.f;
        #pragma unroll
        for (int j = 0; j < 8; j++) s += bexp[j];
        atomicAdd(&g_sumexpv, s);
    }
}

// ---------------- K9: elementwise normalize; block 0 emits context.
__global__ void __launch_bounds__(256) k9_final(float* __restrict__ out,
                                                float* __restrict__ out_ctx) {
    const int t = threadIdx.x;
    if (blockIdx.x == 0) {
        for (int i = t; i < H; i += 256) out_ctx[i] = g_context[i];
    }
    float shift = logf(g_sumexpv);
    int v = blockIdx.x * 256 + t;
    if (v < V) out[v] = g_logits[v] - shift;
}

extern "C" void kernel_launch(void* const* d_in, const int* in_sizes, int n_in,
                              void* d_out, int out_size) {
    const int*   word     = (const int*)  d_in[0];
    const float* last_ctx = (const float*)d_in[1];
    const float* last_hid = (const float*)d_in[2];
    const float* enc      = (const float*)d_in[3];
    const float* emb      = (const float*)d_in[4];
    const float* W_ih0    = (const float*)d_in[5];
    const float* W_hh0    = (const float*)d_in[6];
    const float* b_ih0    = (const float*)d_in[7];
    const float* b_hh0    = (const float*)d_in[8];
    const float* W_ih1    = (const float*)d_in[9];
    const float* W_hh1    = (const float*)d_in[10];
    const float* b_ih1    = (const float*)d_in[11];
    const float* b_hh1    = (const float*)d_in[12];
    const float* Wa       = (const float*)d_in[13];
    // d_in[14] = ba (cancels under softmax shift-invariance)
    const float* W_out    = (const float*)d_in[15];
    const float* b_out    = (const float*)d_in[16];
    float* out = (float*)d_out;

    kG1<<<2*H, 256>>>(word, emb, last_ctx, last_hid,
                      W_ih0, W_hh0, b_ih0, b_hh0, W_hh1,
                      out + OUT_HID);
    kG2<<<H, 256>>>(W_ih1, b_ih1, b_hh1, last_hid, out + OUT_HID + H);
    kA<<<GRID_A, 256>>>(Wa, enc, W_out, out + OUT_ATTN);
    kB<<<NBK, 256>>>(W_out, b_out);
    k9_final<<<(V + 255) / 256, 256>>>(out, out + OUT_CTX);
}

// round 15
// speedup vs baseline: 1.1155x; 1.0210x over previous
#include <cuda_runtime.h>
#include <math.h>

#define V 50257
#define H 1024
#define S 2048
#define NATTN 128               // attention blocks (wave-1 resident by ID)
#define NBK 6283                // ceil(V/8), 8 rows per logits group
#define NPERS 888               // persistent logits blocks (~6/SM * 148)
#define GRID_A (NATTN + NPERS)

// out layout: [0,V) log_softmax | [V,V+H) context | [V+H,V+3H) hidden | [V+3H,V+3H+S) attn
#define OUT_CTX  (V)
#define OUT_HID  (V + H)
#define OUT_ATTN (V + 3*H)

// float4-accessed globals MUST be 16B aligned (round-4 trap)
__device__ __align__(16) float g_h0[H];
__device__ __align__(16) float g_h1[H];
__device__ __align__(16) float g_v[H];
__device__ __align__(16) float g_context[H];
__device__ __align__(16) float g_logits[V];
__device__ __align__(16) float g_part[NBK * 8];   // h1-half partial per row
__device__ __align__(16) float g_gh1[3 * H];      // GRU1 hidden-gate partials
__device__ float g_apm[NATTN];
__device__ float g_aps[NATTN];
__device__ float g_sumexpv;        // global sum of exp(logit), shift 0 (logits are O(1))
__device__ unsigned g_barrier;     // attention-internal barrier
__device__ unsigned g_work_a;      // work-steal counter for kA logits groups
__device__ unsigned g_work_b;      // work-steal counter for kB groups

__device__ __forceinline__ float warp_sum(float v) {
    #pragma unroll
    for (int o = 16; o; o >>= 1) v += __shfl_down_sync(0xffffffffu, v, o);
    return v;
}
__device__ __forceinline__ float warp_max(float v) {
    #pragma unroll
    for (int o = 16; o; o >>= 1) v = fmaxf(v, __shfl_down_sync(0xffffffffu, v, o));
    return v;
}
__device__ __forceinline__ float dot4(float4 a, float4 b) {
    return a.x*b.x + a.y*b.y + a.z*b.z + a.w*b.w;
}
// barrier among the NATTN attention blocks only (IDs 0..127 -> wave-1 resident)
__device__ __forceinline__ void attn_barrier(unsigned target) {
    __syncthreads();
    if (threadIdx.x == 0) {
        __threadfence();
        atomicAdd(&g_barrier, 1u);
        volatile unsigned* p = &g_barrier;
        while (*p < target) __nanosleep(32);
        __threadfence();
    }
    __syncthreads();
}

// ---------------- G1: blocks [0,H): GRU0 row k (x = [emb[word], last_ctx]).
// blocks [H,2H): GRU1 hidden-gate partials gh1 = W_hh1 · last_hid1 (indep of h0).
__global__ void __launch_bounds__(256) kG1(const int* __restrict__ word,
                                           const float* __restrict__ emb,
                                           const float* __restrict__ last_ctx,
                                           const float* __restrict__ last_hid,
                                           const float* __restrict__ W_ih0,
                                           const float* __restrict__ W_hh0,
                                           const float* __restrict__ b_ih0,
                                           const float* __restrict__ b_hh0,
                                           const float* __restrict__ W_hh1,
                                           float* __restrict__ out_hidden0) {
    const int t = threadIdx.x;                 // 256
    const int w = t >> 5, lane = t & 31;
    __shared__ float red[6][8];

    if (blockIdx.x < H) {
        // ===== GRU0 row k =====
        const int k = blockIdx.x;
        if (t == 0) {
            g_v[k] = 0.f;
            g_context[k] = 0.f;
            if (k == 0) {
                g_barrier = 0u; g_sumexpv = 0.f;
                g_work_a = 0u; g_work_b = 0u;
            }
        }
        int wi = word[0];
        const float4* xa4 = (const float4*)(emb + (size_t)wi * H);
        const float4* xb4 = (const float4*)last_ctx;
        const float4* h4  = (const float4*)last_hid;      // hidden layer 0
        float acc[6];
        #pragma unroll
        for (int g = 0; g < 3; g++) {
            const float* wrow = W_ih0 + (size_t)(g * H + k) * (2*H);
            float a  = dot4(((const float4*)wrow)[t],       xa4[t]);
            a       += dot4(((const float4*)(wrow + H))[t], xb4[t]);
            acc[g] = a;
        }
        #pragma unroll
        for (int g = 0; g < 3; g++) {
            const float* wrow = W_hh0 + (size_t)(g * H + k) * H;
            acc[3 + g] = dot4(((const float4*)wrow)[t], h4[t]);
        }
        #pragma unroll
        for (int g = 0; g < 6; g++) {
            float s = warp_sum(acc[g]);
            if (lane == 0) red[g][w] = s;
        }
        __syncthreads();
        if (t == 0) {
            float s[6];
            #pragma unroll
            for (int g = 0; g < 6; g++) {
                float a = 0.f;
                #pragma unroll
                for (int j = 0; j < 8; j++) a += red[g][j];
                s[g] = a;
            }
            float ir = s[0] + b_ih0[k],       hr = s[3] + b_hh0[k];
            float iz = s[1] + b_ih0[H + k],   hz = s[4] + b_hh0[H + k];
            float in_= s[2] + b_ih0[2*H + k], hn = s[5] + b_hh0[2*H + k];
            float r = 1.f / (1.f + expf(-(ir + hr)));
            float z = 1.f / (1.f + expf(-(iz + hz)));
            float n = tanhf(in_ + r * hn);
            float hv = (1.f - z) * n + z * last_hid[k];
            g_h0[k] = hv;
            out_hidden0[k] = hv;
        }
    } else {
        // ===== GRU1 gh partials for row k =====
        const int k = blockIdx.x - H;
        const float4* h4 = (const float4*)(last_hid + H); // hidden layer 1
        float acc[3];
        #pragma unroll
        for (int g = 0; g < 3; g++) {
            const float* wrow = W_hh1 + (size_t)(g * H + k) * H;
            acc[g] = dot4(((const float4*)wrow)[t], h4[t]);
        }
        #pragma unroll
        for (int g = 0; g < 3; g++) {
            float s = warp_sum(acc[g]);
            if (lane == 0) red[g][w] = s;
        }
        __syncthreads();
        if (t == 0) {
            #pragma unroll
            for (int g = 0; g < 3; g++) {
                float a = 0.f;
                #pragma unroll
                for (int j = 0; j < 8; j++) a += red[g][j];
                g_gh1[g * H + k] = a;
            }
        }
    }
}

// ---------------- G2: GRU1 input gates gi = W_ih1 · h0; combine with g_gh1.
__global__ void __launch_bounds__(256) kG2(const float* __restrict__ W_ih1,
                                           const float* __restrict__ b_ih1,
                                           const float* __restrict__ b_hh1,
                                           const float* __restrict__ last_hid,
                                           float* __restrict__ out_hidden1) {
    const int k = blockIdx.x;
    const int t = threadIdx.x;
    const int w = t >> 5, lane = t & 31;
    __shared__ float red[3][8];
    const float4* x4 = (const float4*)g_h0;
    float acc[3];
    #pragma unroll
    for (int g = 0; g < 3; g++) {
        const float* wrow = W_ih1 + (size_t)(g * H + k) * H;
        acc[g] = dot4(((const float4*)wrow)[t], x4[t]);
    }
    #pragma unroll
    for (int g = 0; g < 3; g++) {
        float s = warp_sum(acc[g]);
        if (lane == 0) red[g][w] = s;
    }
    __syncthreads();
    if (t == 0) {
        float s[3];
        #pragma unroll
        for (int g = 0; g < 3; g++) {
            float a = 0.f;
            #pragma unroll
            for (int j = 0; j < 8; j++) a += red[g][j];
            s[g] = a;
        }
        float hprev = last_hid[H + k];
        float ir = s[0] + b_ih1[k],       hr = g_gh1[k]       + b_hh1[k];
        float iz = s[1] + b_ih1[H + k],   hz = g_gh1[H + k]   + b_hh1[H + k];
        float in_= s[2] + b_ih1[2*H + k], hn = g_gh1[2*H + k] + b_hh1[2*H + k];
        float r = 1.f / (1.f + expf(-(ir + hr)));
        float z = 1.f / (1.f + expf(-(iz + hz)));
        float n = tanhf(in_ + r * hn);
        float hv = (1.f - z) * n + z * hprev;
        g_h1[k] = hv;
        out_hidden1[k] = hv;
    }
}

// ---------------- Kernel A: blocks [0,NATTN) fused attention (independent);
// blocks [NATTN,GRID_A): persistent work-stealing over h1-half row groups.
__global__ void __launch_bounds__(256, 6) kA(const float* __restrict__ Wa,
                                             const float* __restrict__ enc,
                                             const float* __restrict__ Wout,
                                             float* __restrict__ out_attn) {
    const int t = threadIdx.x;
    const int w = t >> 5, lane = t & 31;

    if (blockIdx.x < NATTN) {
        // ===== attention =====
        const int b = blockIdx.x;
        __shared__ float h1s[8];
        __shared__ float sc[16];
        __shared__ float attnw[16];
        __shared__ float red[8];
        __shared__ float sM, sInvS;

        if (t < 8) h1s[t] = g_h1[b * 8 + t];
        __syncthreads();
        {
            const float4* Wa4 = (const float4*)(Wa + (size_t)(b * 8) * H);
            float4 a = make_float4(0.f, 0.f, 0.f, 0.f);
            #pragma unroll
            for (int j = 0; j < 8; j++) {
                float4 wv = Wa4[j * 256 + t];
                float hv = h1s[j];
                a.x += wv.x * hv; a.y += wv.y * hv; a.z += wv.z * hv; a.w += wv.w * hv;
            }
            atomicAdd(&g_v[4*t + 0], a.x);
            atomicAdd(&g_v[4*t + 1], a.y);
            atomicAdd(&g_v[4*t + 2], a.z);
            atomicAdd(&g_v[4*t + 3], a.w);
        }
        attn_barrier(NATTN);

        const int s0 = b * 16;
        {
            const float4* v4 = (const float4*)g_v;
            float4 vv[8];
            #pragma unroll
            for (int i = 0; i < 8; i++) vv[i] = v4[lane + 32*i];
            const float4* e4a = (const float4*)(enc + (size_t)(s0 + 2*w)     * H);
            const float4* e4b = (const float4*)(enc + (size_t)(s0 + 2*w + 1) * H);
            float acc0 = 0.f, acc1 = 0.f;
            #pragma unroll
            for (int i = 0; i < 8; i++) {
                acc0 += dot4(e4a[lane + 32*i], vv[i]);
                acc1 += dot4(e4b[lane + 32*i], vv[i]);
            }
            acc0 = warp_sum(acc0);
            acc1 = warp_sum(acc1);
            if (lane == 0) { sc[2*w] = acc0; sc[2*w + 1] = acc1; }
        }
        __syncthreads();
        if (t == 0) {
            float m = -INFINITY;
            #pragma unroll
            for (int j = 0; j < 16; j++) m = fmaxf(m, sc[j]);
            float s = 0.f;
            #pragma unroll
            for (int j = 0; j < 16; j++) s += expf(sc[j] - m);
            g_apm[b] = m;
            g_aps[b] = s;
        }
        attn_barrier(2 * NATTN);

        {
            float m = (t < NATTN) ? g_apm[t] : -INFINITY;
            m = warp_max(m);
            if (lane == 0) red[w] = m;
            __syncthreads();
            if (t == 0) {
                float M = -INFINITY;
                #pragma unroll
                for (int j = 0; j < 8; j++) M = fmaxf(M, red[j]);
                sM = M;
            }
            __syncthreads();
            float e = (t < NATTN) ? g_aps[t] * expf(g_apm[t] - sM) : 0.f;
            e = warp_sum(e);
            if (lane == 0) red[w] = e;
            __syncthreads();
            if (t == 0) {
                float Ssum = 0.f;
                #pragma unroll
                for (int j = 0; j < 8; j++) Ssum += red[j];
                sInvS = 1.f / Ssum;
            }
            __syncthreads();
            if (t < 16) {
                float a = expf(sc[t] - sM) * sInvS;
                attnw[t] = a;
                out_attn[s0 + t] = a;
            }
            __syncthreads();
        }
        {
            const float4* e4 = (const float4*)(enc + (size_t)s0 * H);
            float4 c = make_float4(0.f, 0.f, 0.f, 0.f);
            #pragma unroll
            for (int r = 0; r < 16; r++) {
                float av = attnw[r];
                float4 e = e4[r * 256 + t];
                c.x += av * e.x; c.y += av * e.y; c.z += av * e.z; c.w += av * e.w;
            }
            atomicAdd(&g_context[4*t + 0], c.x);
            atomicAdd(&g_context[4*t + 1], c.y);
            atomicAdd(&g_context[4*t + 2], c.z);
            atomicAdd(&g_context[4*t + 3], c.w);
        }
    } else {
        // ===== h1-half logits, persistent work-stealing (1 row/warp, __ldcs) =====
        __shared__ __align__(16) float qs[H];
        __shared__ int s_grp;
        for (int i = t; i < H; i += 256) qs[i] = g_h1[i];
        const float4* q4 = (const float4*)qs;
        for (;;) {
            if (t == 0) s_grp = (int)atomicAdd(&g_work_a, 1u);
            __syncthreads();
            const int grp = s_grp;
            __syncthreads();
            if (grp >= NBK) break;
            const int r = grp * 8 + w;
            if (r < V) {
                const float4* wr = (const float4*)(Wout + (size_t)r * (2*H));
                float acc0 = 0.f, acc1 = 0.f;
                #pragma unroll
                for (int i = 0; i < 8; i += 2) {
                    acc0 += dot4(__ldcs(&wr[lane + i*32]),     q4[lane + i*32]);
                    acc1 += dot4(__ldcs(&wr[lane + (i+1)*32]), q4[lane + (i+1)*32]);
                }
                float acc = warp_sum(acc0 + acc1);
                if (lane == 0) g_part[r] = acc;
            }
        }
    }
}

// ---------------- Kernel B: ctx-half, persistent work-stealing; combine ->
// logits; per-block sum-exp accumulated across groups, one atomicAdd at end.
__global__ void __launch_bounds__(256, 6) kB(const float* __restrict__ Wout,
                                             const float* __restrict__ bout) {
    const int t = threadIdx.x;
    const int w = t >> 5, lane = t & 31;
    __shared__ __align__(16) float qs[H];
    __shared__ float bexp[8];
    __shared__ int s_grp;
    for (int i = t; i < H; i += 256) qs[i] = g_context[i];
    const float4* q4 = (const float4*)qs;

    float e_acc = 0.f;
    for (;;) {
        if (t == 0) s_grp = (int)atomicAdd(&g_work_b, 1u);
        __syncthreads();
        const int grp = s_grp;
        __syncthreads();
        if (grp >= NBK) break;
        const int r = grp * 8 + w;
        if (r < V) {
            const float4* wr = (const float4*)(Wout + (size_t)r * (2*H) + H);
            float acc0 = 0.f, acc1 = 0.f;
            #pragma unroll
            for (int i = 0; i < 8; i += 2) {
                acc0 += dot4(__ldcs(&wr[lane + i*32]),     q4[lane + i*32]);
                acc1 += dot4(__ldcs(&wr[lane + (i+1)*32]), q4[lane + (i+1)*32]);
            }
            float acc = warp_sum(acc0 + acc1);
            if (lane == 0) {
                float logit = acc + g_part[r] + bout[r];
                g_logits[r] = logit;
                e_acc += expf(logit);
            }
        }
    }
    if (lane == 0) bexp[w] = e_acc;
    __syncthreads();
    if (t == 0) {
        float s = 0.f;
        #pragma unroll
        for (int j = 0; j < 8; j++) s += bexp[j];
        atomicAdd(&g_sumexpv, s);
    }
}

// ---------------- K9: elementwise normalize; block 0 emits context.
__global__ void __launch_bounds__(256) k9_final(float* __restrict__ out,
                                                float* __restrict__ out_ctx) {
    const int t = threadIdx.x;
    if (blockIdx.x == 0) {
        for (int i = t; i < H; i += 256) out_ctx[i] = g_context[i];
    }
    float shift = logf(g_sumexpv);
    int v = blockIdx.x * 256 + t;
    if (v < V) out[v] = g_logits[v] - shift;
}

extern "C" void kernel_launch(void* const* d_in, const int* in_sizes, int n_in,
                              void* d_out, int out_size) {
    const int*   word     = (const int*)  d_in[0];
    const float* last_ctx = (const float*)d_in[1];
    const float* last_hid = (const float*)d_in[2];
    const float* enc      = (const float*)d_in[3];
    const float* emb      = (const float*)d_in[4];
    const float* W_ih0    = (const float*)d_in[5];
    const float* W_hh0    = (const float*)d_in[6];
    const float* b_ih0    = (const float*)d_in[7];
    const float* b_hh0    = (const float*)d_in[8];
    const float* W_ih1    = (const float*)d_in[9];
    const float* W_hh1    = (const float*)d_in[10];
    const float* b_ih1    = (const float*)d_in[11];
    const float* b_hh1    = (const float*)d_in[12];
    const float* Wa       = (const float*)d_in[13];
    // d_in[14] = ba (cancels under softmax shift-invariance)
    const float* W_out    = (const float*)d_in[15];
    const float* b_out    = (const float*)d_in[16];
    float* out = (float*)d_out;

    kG1<<<2*H, 256>>>(word, emb, last_ctx, last_hid,
                      W_ih0, W_hh0, b_ih0, b_hh0, W_hh1,
                      out + OUT_HID);
    kG2<<<H, 256>>>(W_ih1, b_ih1, b_hh1, last_hid, out + OUT_HID + H);
    kA<<<GRID_A, 256>>>(Wa, enc, W_out, out + OUT_ATTN);
    kB<<<NPERS, 256>>>(W_out, b_out);
    k9_final<<<(V + 255) / 256, 256>>>(out, out + OUT_CTX);
}

// round 16
// speedup vs baseline: 1.1803x; 1.0582x over previous
#include <cuda_runtime.h>
#include <math.h>

#define V 50257
#define H 1024
#define S 2048
#define NATTN 128               // attention blocks (wave-1 resident by ID)
#define NBK 6283                // ceil(V/8), 8 rows per logits group
#define NPERS 760               // logits-only blocks; total grid = 888 = 6/SM * 148
#define GRID_MAIN (NATTN + NPERS)
#define SENT_BITS 0x7FC0DEADu   // NaN sentinel marking "g_part not ready"

// out layout: [0,V) log_softmax | [V,V+H) context | [V+H,V+3H) hidden | [V+3H,V+3H+S) attn
#define OUT_CTX  (V)
#define OUT_HID  (V + H)
#define OUT_ATTN (V + 3*H)

// float4-accessed globals MUST be 16B aligned (round-4 trap)
__device__ __align__(16) float g_h0[H];
__device__ __align__(16) float g_h1[H];
__device__ __align__(16) float g_v[H];
__device__ __align__(16) float g_context[H];
__device__ __align__(16) float g_logits[V];
__device__ __align__(16) float g_part[NBK * 8];   // h1-half partial per row (sentinel-init)
__device__ __align__(16) float g_gh1[3 * H];      // GRU1 hidden-gate partials
__device__ float g_apm[NATTN];
__device__ float g_aps[NATTN];
__device__ float g_sumexpv;        // global sum of exp(logit), shift 0 (logits are O(1))
__device__ unsigned g_barrier;     // attention-internal barrier
__device__ unsigned g_ctx_done;    // context-ready counter (target NATTN)
__device__ unsigned g_work_a;      // work-steal counter: h1-half groups
__device__ unsigned g_work_b;      // work-steal counter: ctx-half groups

__device__ __forceinline__ float warp_sum(float v) {
    #pragma unroll
    for (int o = 16; o; o >>= 1) v += __shfl_down_sync(0xffffffffu, v, o);
    return v;
}
__device__ __forceinline__ float warp_max(float v) {
    #pragma unroll
    for (int o = 16; o; o >>= 1) v = fmaxf(v, __shfl_down_sync(0xffffffffu, v, o));
    return v;
}
__device__ __forceinline__ float dot4(float4 a, float4 b) {
    return a.x*b.x + a.y*b.y + a.z*b.z + a.w*b.w;
}
// barrier among the NATTN attention blocks only (IDs 0..127 -> wave-1 resident)
__device__ __forceinline__ void attn_barrier(unsigned target) {
    __syncthreads();
    if (threadIdx.x == 0) {
        __threadfence();
        atomicAdd(&g_barrier, 1u);
        volatile unsigned* p = &g_barrier;
        while (*p < target) __nanosleep(32);
        __threadfence();
    }
    __syncthreads();
}

// ---------------- G1: blocks [0,H): GRU0 row k (x = [emb[word], last_ctx]).
// blocks [H,2H): GRU1 hidden-gate partials gh1 = W_hh1 · last_hid1 (indep of h0).
// Also: sentinel-init g_part, reset counters.
__global__ void __launch_bounds__(256) kG1(const int* __restrict__ word,
                                           const float* __restrict__ emb,
                                           const float* __restrict__ last_ctx,
                                           const float* __restrict__ last_hid,
                                           const float* __restrict__ W_ih0,
                                           const float* __restrict__ W_hh0,
                                           const float* __restrict__ b_ih0,
                                           const float* __restrict__ b_hh0,
                                           const float* __restrict__ W_hh1,
                                           float* __restrict__ out_hidden0) {
    const int t = threadIdx.x;                 // 256
    const int w = t >> 5, lane = t & 31;
    __shared__ float red[6][8];

    // sentinel-init g_part (covered by blocks 0..196)
    {
        int pidx = blockIdx.x * 256 + t;
        if (pidx < NBK * 8) g_part[pidx] = __int_as_float((int)SENT_BITS);
    }

    if (blockIdx.x < H) {
        // ===== GRU0 row k =====
        const int k = blockIdx.x;
        if (t == 0) {
            g_v[k] = 0.f;
            g_context[k] = 0.f;
            if (k == 0) {
                g_barrier = 0u; g_sumexpv = 0.f;
                g_ctx_done = 0u; g_work_a = 0u; g_work_b = 0u;
            }
        }
        int wi = word[0];
        const float4* xa4 = (const float4*)(emb + (size_t)wi * H);
        const float4* xb4 = (const float4*)last_ctx;
        const float4* h4  = (const float4*)last_hid;      // hidden layer 0
        float acc[6];
        #pragma unroll
        for (int g = 0; g < 3; g++) {
            const float* wrow = W_ih0 + (size_t)(g * H + k) * (2*H);
            float a  = dot4(((const float4*)wrow)[t],       xa4[t]);
            a       += dot4(((const float4*)(wrow + H))[t], xb4[t]);
            acc[g] = a;
        }
        #pragma unroll
        for (int g = 0; g < 3; g++) {
            const float* wrow = W_hh0 + (size_t)(g * H + k) * H;
            acc[3 + g] = dot4(((const float4*)wrow)[t], h4[t]);
        }
        #pragma unroll
        for (int g = 0; g < 6; g++) {
            float s = warp_sum(acc[g]);
            if (lane == 0) red[g][w] = s;
        }
        __syncthreads();
        if (t == 0) {
            float s[6];
            #pragma unroll
            for (int g = 0; g < 6; g++) {
                float a = 0.f;
                #pragma unroll
                for (int j = 0; j < 8; j++) a += red[g][j];
                s[g] = a;
            }
            float ir = s[0] + b_ih0[k],       hr = s[3] + b_hh0[k];
            float iz = s[1] + b_ih0[H + k],   hz = s[4] + b_hh0[H + k];
            float in_= s[2] + b_ih0[2*H + k], hn = s[5] + b_hh0[2*H + k];
            float r = 1.f / (1.f + expf(-(ir + hr)));
            float z = 1.f / (1.f + expf(-(iz + hz)));
            float n = tanhf(in_ + r * hn);
            float hv = (1.f - z) * n + z * last_hid[k];
            g_h0[k] = hv;
            out_hidden0[k] = hv;
        }
    } else {
        // ===== GRU1 gh partials for row k =====
        const int k = blockIdx.x - H;
        const float4* h4 = (const float4*)(last_hid + H); // hidden layer 1
        float acc[3];
        #pragma unroll
        for (int g = 0; g < 3; g++) {
            const float* wrow = W_hh1 + (size_t)(g * H + k) * H;
            acc[g] = dot4(((const float4*)wrow)[t], h4[t]);
        }
        #pragma unroll
        for (int g = 0; g < 3; g++) {
            float s = warp_sum(acc[g]);
            if (lane == 0) red[g][w] = s;
        }
        __syncthreads();
        if (t == 0) {
            #pragma unroll
            for (int g = 0; g < 3; g++) {
                float a = 0.f;
                #pragma unroll
                for (int j = 0; j < 8; j++) a += red[g][j];
                g_gh1[g * H + k] = a;
            }
        }
    }
}

// ---------------- G2: GRU1 input gates gi = W_ih1 · h0; combine with g_gh1.
__global__ void __launch_bounds__(256) kG2(const float* __restrict__ W_ih1,
                                           const float* __restrict__ b_ih1,
                                           const float* __restrict__ b_hh1,
                                           const float* __restrict__ last_hid,
                                           float* __restrict__ out_hidden1) {
    const int k = blockIdx.x;
    const int t = threadIdx.x;
    const int w = t >> 5, lane = t & 31;
    __shared__ float red[3][8];
    const float4* x4 = (const float4*)g_h0;
    float acc[3];
    #pragma unroll
    for (int g = 0; g < 3; g++) {
        const float* wrow = W_ih1 + (size_t)(g * H + k) * H;
        acc[g] = dot4(((const float4*)wrow)[t], x4[t]);
    }
    #pragma unroll
    for (int g = 0; g < 3; g++) {
        float s = warp_sum(acc[g]);
        if (lane == 0) red[g][w] = s;
    }
    __syncthreads();
    if (t == 0) {
        float s[3];
        #pragma unroll
        for (int g = 0; g < 3; g++) {
            float a = 0.f;
            #pragma unroll
            for (int j = 0; j < 8; j++) a += red[g][j];
            s[g] = a;
        }
        float hprev = last_hid[H + k];
        float ir = s[0] + b_ih1[k],       hr = g_gh1[k]       + b_hh1[k];
        float iz = s[1] + b_ih1[H + k],   hz = g_gh1[H + k]   + b_hh1[H + k];
        float in_= s[2] + b_ih1[2*H + k], hn = g_gh1[2*H + k] + b_hh1[2*H + k];
        float r = 1.f / (1.f + expf(-(ir + hr)));
        float z = 1.f / (1.f + expf(-(iz + hz)));
        float n = tanhf(in_ + r * hn);
        float hv = (1.f - z) * n + z * hprev;
        g_h1[k] = hv;
        out_hidden1[k] = hv;
    }
}

// ---------------- Main: blocks [0,NATTN) do attention first, then join logits
// work-stealing. Phase A: h1-half -> g_part (value doubles as ready flag via
// NaN sentinel). Phase B: ctx-half + g_part -> logits + sum-exp.
__global__ void __launch_bounds__(256, 6) kMain(const float* __restrict__ Wa,
                                                const float* __restrict__ enc,
                                                const float* __restrict__ Wout,
                                                const float* __restrict__ bout,
                                                float* __restrict__ out_attn) {
    const int t = threadIdx.x;
    const int w = t >> 5, lane = t & 31;

    __shared__ __align__(16) float qs[H];
    __shared__ float smem_red[8];
    __shared__ int s_grp;

    if (blockIdx.x < NATTN) {
        // ================= ATTENTION =================
        const int b = blockIdx.x;
        __shared__ float h1s[8];
        __shared__ float sc[16];
        __shared__ float attnw[16];
        __shared__ float sM, sInvS;

        if (t < 8) h1s[t] = g_h1[b * 8 + t];
        __syncthreads();
        {
            const float4* Wa4 = (const float4*)(Wa + (size_t)(b * 8) * H);
            float4 a = make_float4(0.f, 0.f, 0.f, 0.f);
            #pragma unroll
            for (int j = 0; j < 8; j++) {
                float4 wv = Wa4[j * 256 + t];
                float hv = h1s[j];
                a.x += wv.x * hv; a.y += wv.y * hv; a.z += wv.z * hv; a.w += wv.w * hv;
            }
            atomicAdd(&g_v[4*t + 0], a.x);
            atomicAdd(&g_v[4*t + 1], a.y);
            atomicAdd(&g_v[4*t + 2], a.z);
            atomicAdd(&g_v[4*t + 3], a.w);
        }
        attn_barrier(NATTN);

        const int s0 = b * 16;
        {
            const float4* v4 = (const float4*)g_v;
            float4 vv[8];
            #pragma unroll
            for (int i = 0; i < 8; i++) vv[i] = v4[lane + 32*i];
            const float4* e4a = (const float4*)(enc + (size_t)(s0 + 2*w)     * H);
            const float4* e4b = (const float4*)(enc + (size_t)(s0 + 2*w + 1) * H);
            float acc0 = 0.f, acc1 = 0.f;
            #pragma unroll
            for (int i = 0; i < 8; i++) {
                acc0 += dot4(e4a[lane + 32*i], vv[i]);
                acc1 += dot4(e4b[lane + 32*i], vv[i]);
            }
            acc0 = warp_sum(acc0);
            acc1 = warp_sum(acc1);
            if (lane == 0) { sc[2*w] = acc0; sc[2*w + 1] = acc1; }
        }
        __syncthreads();
        if (t == 0) {
            float m = -INFINITY;
            #pragma unroll
            for (int j = 0; j < 16; j++) m = fmaxf(m, sc[j]);
            float s = 0.f;
            #pragma unroll
            for (int j = 0; j < 16; j++) s += expf(sc[j] - m);
            g_apm[b] = m;
            g_aps[b] = s;
        }
        attn_barrier(2 * NATTN);

        {
            float m = (t < NATTN) ? g_apm[t] : -INFINITY;
            m = warp_max(m);
            if (lane == 0) smem_red[w] = m;
            __syncthreads();
            if (t == 0) {
                float M = -INFINITY;
                #pragma unroll
                for (int j = 0; j < 8; j++) M = fmaxf(M, smem_red[j]);
                sM = M;
            }
            __syncthreads();
            float e = (t < NATTN) ? g_aps[t] * expf(g_apm[t] - sM) : 0.f;
            e = warp_sum(e);
            if (lane == 0) smem_red[w] = e;
            __syncthreads();
            if (t == 0) {
                float Ssum = 0.f;
                #pragma unroll
                for (int j = 0; j < 8; j++) Ssum += smem_red[j];
                sInvS = 1.f / Ssum;
            }
            __syncthreads();
            if (t < 16) {
                float a = expf(sc[t] - sM) * sInvS;
                attnw[t] = a;
                out_attn[s0 + t] = a;
            }
            __syncthreads();
        }
        {
            const float4* e4 = (const float4*)(enc + (size_t)s0 * H);
            float4 c = make_float4(0.f, 0.f, 0.f, 0.f);
            #pragma unroll
            for (int r = 0; r < 16; r++) {
                float av = attnw[r];
                float4 e = e4[r * 256 + t];
                c.x += av * e.x; c.y += av * e.y; c.z += av * e.z; c.w += av * e.w;
            }
            atomicAdd(&g_context[4*t + 0], c.x);
            atomicAdd(&g_context[4*t + 1], c.y);
            atomicAdd(&g_context[4*t + 2], c.z);
            atomicAdd(&g_context[4*t + 3], c.w);
        }
        __syncthreads();
        if (t == 0) {
            __threadfence();
            atomicAdd(&g_ctx_done, 1u);
        }
        __syncthreads();
        // fall through: join logits work-stealing
    }

    // ================= PHASE A: h1-half -> g_part =================
    for (int i = t; i < H; i += 256) qs[i] = g_h1[i];
    __syncthreads();
    {
        const float4* q4 = (const float4*)qs;
        for (;;) {
            if (t == 0) s_grp = (int)atomicAdd(&g_work_a, 1u);
            __syncthreads();
            const int grp = s_grp;
            __syncthreads();
            if (grp >= NBK) break;
            const int r = grp * 8 + w;
            if (r < V) {
                const float4* wr = (const float4*)(Wout + (size_t)r * (2*H));
                float acc0 = 0.f, acc1 = 0.f;
                #pragma unroll
                for (int i = 0; i < 8; i += 2) {
                    acc0 += dot4(__ldcs(&wr[lane + i*32]),     q4[lane + i*32]);
                    acc1 += dot4(__ldcs(&wr[lane + (i+1)*32]), q4[lane + (i+1)*32]);
                }
                float acc = warp_sum(acc0 + acc1);
                // value IS the ready flag (sentinel-init); single-word handshake
                if (lane == 0) g_part[r] = acc;
            }
        }
    }

    // ================= PHASE B: ctx-half + g_part -> logits =================
    if (t == 0) {
        volatile unsigned* p = &g_ctx_done;
        while (*p < NATTN) __nanosleep(64);   // attention done ~15us; A drains ~37us -> ~0 spin
        __threadfence();
    }
    __syncthreads();
    for (int i = t; i < H; i += 256) qs[i] = __ldcg(&g_context[i]);
    __syncthreads();
    {
        const float4* q4 = (const float4*)qs;
        float e_acc = 0.f;
        for (;;) {
            if (t == 0) s_grp = (int)atomicAdd(&g_work_b, 1u);
            __syncthreads();
            const int grp = s_grp;
            __syncthreads();
            if (grp >= NBK) break;
            const int r = grp * 8 + w;
            if (r < V) {
                const float4* wr = (const float4*)(Wout + (size_t)r * (2*H) + H);
                float acc0 = 0.f, acc1 = 0.f;
                #pragma unroll
                for (int i = 0; i < 8; i += 2) {
                    acc0 += dot4(__ldcs(&wr[lane + i*32]),     q4[lane + i*32]);
                    acc1 += dot4(__ldcs(&wr[lane + (i+1)*32]), q4[lane + (i+1)*32]);
                }
                float acc = warp_sum(acc0 + acc1);
                if (lane == 0) {
                    // per-row ready check: spin until h1-half partial landed
                    float part = __ldcg(&g_part[r]);
                    while (__float_as_int(part) == (int)SENT_BITS) {
                        __nanosleep(32);
                        part = __ldcg(&g_part[r]);
                    }
                    float logit = acc + part + bout[r];
                    g_logits[r] = logit;
                    e_acc += expf(logit);
                }
            }
        }
        if (lane == 0) smem_red[w] = e_acc;
        __syncthreads();
        if (t == 0) {
            float s = 0.f;
            #pragma unroll
            for (int j = 0; j < 8; j++) s += smem_red[j];
            atomicAdd(&g_sumexpv, s);
        }
    }
}

// ---------------- K9: elementwise normalize; block 0 emits context.
__global__ void __launch_bounds__(256) k9_final(float* __restrict__ out,
                                                float* __restrict__ out_ctx) {
    const int t = threadIdx.x;
    if (blockIdx.x == 0) {
        for (int i = t; i < H; i += 256) out_ctx[i] = g_context[i];
    }
    float shift = logf(g_sumexpv);
    int v = blockIdx.x * 256 + t;
    if (v < V) out[v] = g_logits[v] - shift;
}

extern "C" void kernel_launch(void* const* d_in, const int* in_sizes, int n_in,
                              void* d_out, int out_size) {
    const int*   word     = (const int*)  d_in[0];
    const float* last_ctx = (const float*)d_in[1];
    const float* last_hid = (const float*)d_in[2];
    const float* enc      = (const float*)d_in[3];
    const float* emb      = (const float*)d_in[4];
    const float* W_ih0    = (const float*)d_in[5];
    const float* W_hh0    = (const float*)d_in[6];
    const float* b_ih0    = (const float*)d_in[7];
    const float* b_hh0    = (const float*)d_in[8];
    const float* W_ih1    = (const float*)d_in[9];
    const float* W_hh1    = (const float*)d_in[10];
    const float* b_ih1    = (const float*)d_in[11];
    const float* b_hh1    = (const float*)d_in[12];
    const float* Wa       = (const float*)d_in[13];
    // d_in[14] = ba (cancels under softmax shift-invariance)
    const float* W_out    = (const float*)d_in[15];
    const float* b_out    = (const float*)d_in[16];
    float* out = (float*)d_out;

    kG1<<<2*H, 256>>>(word, emb, last_ctx, last_hid,
                      W_ih0, W_hh0, b_ih0, b_hh0, W_hh1,
                      out + OUT_HID);
    kG2<<<H, 256>>>(W_ih1, b_ih1, b_hh1, last_hid, out + OUT_HID + H);
    kMain<<<GRID_MAIN, 256>>>(Wa, enc, W_out, b_out, out + OUT_ATTN);
    k9_final<<<(V + 255) / 256, 256>>>(out, out + OUT_CTX);
}